// round 2
// baseline (speedup 1.0000x reference)
#include <cuda_runtime.h>

typedef unsigned long long ull;

// ---------------------------------------------------------------------------
// Problem constants: B=64, Cin=64, T=300, V=25, K=3, Cout=64
//   x:     [64][64][300][25]  (b, c, t, v)      -> flat (b*64+c)*7500 + q, q=t*25+v
//   W:     [192][64]          (o, c), o = k*64+c_out
//   bias:  [192]
//   A:     [3][25][25]        (k, v, w)
//   out:   [64][64][300][25]  (b, c, t, w)
// Intermediate xc: [b][o][q] = (b*192+o)*7500 + q   (369 MB device scratch)
// ---------------------------------------------------------------------------

__device__ float g_xc[92160000];      // 64*192*7500
__device__ float g_psum[4096];        // [b*64+c]
__device__ float g_psumsq[4096];
__device__ float g_scale[64];
__device__ float g_shift[64];

__device__ __forceinline__ ull pk(float lo, float hi) {
    ull r; asm("mov.b64 %0, {%1,%2};" : "=l"(r) : "f"(lo), "f"(hi)); return r;
}
__device__ __forceinline__ void upk(ull v, float& lo, float& hi) {
    asm("mov.b64 {%0,%1}, %2;" : "=f"(lo), "=f"(hi) : "l"(v));
}
__device__ __forceinline__ ull ffma2(ull a, ull b, ull c) {
    ull d; asm("fma.rn.f32x2 %0, %1, %2, %3;" : "=l"(d) : "l"(a), "l"(b), "l"(c)); return d;
}

// ---------------------------------------------------------------------------
// Kernel 1: conv GEMM. Tile = 64 o x 128 p, K = 64 (fully resident in SMEM).
// Thread tile: 4 o x (4 pairs of p) packed f32x2. grid (3750, 3), block 256.
// ---------------------------------------------------------------------------
__global__ __launch_bounds__(256) void k_conv(const float* __restrict__ x,
                                              const float* __restrict__ W,
                                              const float* __restrict__ bias) {
    __shared__ __align__(16) float sX[64][128];   // [c][p_local]
    __shared__ __align__(16) float sW[64][64];    // [o_local][c]

    const int tid = threadIdx.x;
    const int p0 = blockIdx.x * 128;
    const int o0 = blockIdx.y * 64;

    // Load X tile: each thread owns one p_local, loops over c. Coalesced LDG.
    {
        const int pl = tid & 127;
        const int c0 = tid >> 7;            // 0 or 1
        const int p  = p0 + pl;
        const int b  = p / 7500;
        const int q  = p - b * 7500;
        const float* xb = x + b * 480000 + q;
        #pragma unroll
        for (int c = c0; c < 64; c += 2)
            sX[c][pl] = xb[c * 7500];
    }
    // Load W tile: [o_local][c], coalesced both sides.
    #pragma unroll
    for (int i = tid; i < 4096; i += 256) {
        const int c  = i & 63;
        const int ol = i >> 6;
        sW[ol][c] = W[(o0 + ol) * 64 + c];
    }
    __syncthreads();

    const int tx = tid & 15;     // p-group
    const int ty = tid >> 4;     // o-group

    ull acc[4][4];
    #pragma unroll
    for (int i = 0; i < 4; ++i) {
        const float bv = __ldg(&bias[o0 + ty * 4 + i]);
        const ull bp = pk(bv, bv);
        #pragma unroll
        for (int j = 0; j < 4; ++j) acc[i][j] = bp;
    }

    const ull* sX64 = reinterpret_cast<const ull*>(&sX[0][0]);  // row stride 64 ull

    #pragma unroll 16
    for (int c = 0; c < 64; ++c) {
        ull xp[4];
        #pragma unroll
        for (int j = 0; j < 4; ++j)
            xp[j] = sX64[c * 64 + tx + 16 * j];     // conflict-free LDS.64
        #pragma unroll
        for (int i = 0; i < 4; ++i) {
            const float w = sW[ty * 4 + i][c];       // warp-broadcast
            const ull wp = pk(w, w);
            #pragma unroll
            for (int j = 0; j < 4; ++j)
                acc[i][j] = ffma2(wp, xp[j], acc[i][j]);
        }
    }

    // Store xc: float2 per (o, p-pair). 7500 even -> a pair never straddles b.
    #pragma unroll
    for (int j = 0; j < 4; ++j) {
        const int p = p0 + tx * 2 + 32 * j;
        const int b = p / 7500;
        const int q = p - b * 7500;
        float* dst = g_xc + b * 1440000 + q;
        #pragma unroll
        for (int i = 0; i < 4; ++i) {
            const int o = o0 + ty * 4 + i;
            float lo, hi; upk(acc[i][j], lo, hi);
            *reinterpret_cast<float2*>(dst + o * 7500) = make_float2(lo, hi);
        }
    }
}

// ---------------------------------------------------------------------------
// Kernel 2: graph matmul. out[r][w] = sum_{k,v} xc[r; k,v] * A[k][v][w]
// rows r = (b*64+c)*300 + t. Tile = 128 rows x 32 w (25 live), K = 75.
// xc addr(r,k,v) = b*960000 + k*480000 + r*25 + v  -> 3 contiguous chunks/tile.
// 19200 rows per b, divisible by 128 -> tiles never straddle b.
// grid 9600, block 256 = 32 row-threads x 8 w-threads.
// ---------------------------------------------------------------------------
__global__ __launch_bounds__(256) void k_graph(const float* __restrict__ A,
                                               float* __restrict__ out) {
    __shared__ __align__(16) float sXc[75][130];  // [kv][r_local], pad for ull stride
    __shared__ __align__(16) float sA[75][32];    // zero-padded w

    const int tid = threadIdx.x;
    const int r0 = blockIdx.x * 128;
    const int b  = r0 / 19200;

    for (int i = tid; i < 2400; i += 256) {
        const int w  = i & 31;
        const int kv = i >> 5;
        sA[kv][w] = (w < 25) ? A[kv * 25 + w] : 0.f;
    }
    #pragma unroll
    for (int k = 0; k < 3; ++k) {
        const float* src = g_xc + b * 960000 + k * 480000 + r0 * 25;
        for (int i = tid; i < 3200; i += 256) {
            const int rl = i / 25;
            const int v  = i - rl * 25;
            sXc[k * 25 + v][rl] = src[i];          // contiguous, coalesced LDG
        }
    }
    __syncthreads();

    const int rl = tid & 31;
    const int wt = tid >> 5;

    ull acc[2][4];
    #pragma unroll
    for (int i = 0; i < 2; ++i)
        #pragma unroll
        for (int j = 0; j < 4; ++j) acc[i][j] = 0ULL;

    const ull* sXc64 = reinterpret_cast<const ull*>(&sXc[0][0]);  // row stride 65 ull

    #pragma unroll 15
    for (int kv = 0; kv < 75; ++kv) {
        const float4 av = *reinterpret_cast<const float4*>(&sA[kv][wt * 4]);
        const ull wp0 = pk(av.x, av.x);
        const ull wp1 = pk(av.y, av.y);
        const ull wp2 = pk(av.z, av.z);
        const ull wp3 = pk(av.w, av.w);
        ull xp[2];
        xp[0] = sXc64[kv * 65 + rl];
        xp[1] = sXc64[kv * 65 + rl + 32];
        #pragma unroll
        for (int i = 0; i < 2; ++i) {
            acc[i][0] = ffma2(xp[i], wp0, acc[i][0]);
            acc[i][1] = ffma2(xp[i], wp1, acc[i][1]);
            acc[i][2] = ffma2(xp[i], wp2, acc[i][2]);
            acc[i][3] = ffma2(xp[i], wp3, acc[i][3]);
        }
    }
    __syncthreads();

    // Stage through SMEM (reuse sXc) so global stores are fully coalesced.
    float* sOut = &sXc[0][0];
    #pragma unroll
    for (int i = 0; i < 2; ++i) {
        const int r = rl * 2 + 64 * i;
        #pragma unroll
        for (int j = 0; j < 4; ++j) {
            const int w = wt * 4 + j;
            if (w < 25) {
                float lo, hi; upk(acc[i][j], lo, hi);
                sOut[r * 25 + w]       = lo;
                sOut[(r + 1) * 25 + w] = hi;
            }
        }
    }
    __syncthreads();

    const float4* s4 = reinterpret_cast<const float4*>(sOut);
    float4* d4 = reinterpret_cast<float4*>(out + r0 * 25);   // r0*25 % 4 == 0
    for (int i = tid; i < 800; i += 256)
        d4[i] = s4[i];
}

// ---------------------------------------------------------------------------
// Kernel 3: per-(b,c) partial sum / sumsq over the 7500 contiguous pre-BN floats.
// grid 4096 (bc), block 256. Deterministic (fixed tree, no atomics).
// ---------------------------------------------------------------------------
__global__ __launch_bounds__(256) void k_stats1(const float* __restrict__ out) {
    const int bc = blockIdx.x;
    const float4* p = reinterpret_cast<const float4*>(out + bc * 7500);
    float s = 0.f, sq = 0.f;
    for (int i = threadIdx.x; i < 1875; i += 256) {
        const float4 v = p[i];
        s  += (v.x + v.y) + (v.z + v.w);
        sq += v.x * v.x + v.y * v.y + v.z * v.z + v.w * v.w;
    }
    #pragma unroll
    for (int off = 16; off > 0; off >>= 1) {
        s  += __shfl_down_sync(0xffffffffu, s, off);
        sq += __shfl_down_sync(0xffffffffu, sq, off);
    }
    __shared__ float ws[8], wq[8];
    const int lane = threadIdx.x & 31, wid = threadIdx.x >> 5;
    if (lane == 0) { ws[wid] = s; wq[wid] = sq; }
    __syncthreads();
    if (threadIdx.x < 8) {
        s = ws[threadIdx.x]; sq = wq[threadIdx.x];
        #pragma unroll
        for (int off = 4; off > 0; off >>= 1) {
            s  += __shfl_down_sync(0xffu, s, off);
            sq += __shfl_down_sync(0xffu, sq, off);
        }
        if (threadIdx.x == 0) { g_psum[bc] = s; g_psumsq[bc] = sq; }
    }
}

// ---------------------------------------------------------------------------
// Kernel 4: combine 64 per-b partials per channel (double), fold gamma/beta.
// grid 64 (c), block 64 (b).
// ---------------------------------------------------------------------------
__global__ void k_stats2(const float* __restrict__ gamma,
                         const float* __restrict__ beta) {
    const int c = blockIdx.x;
    const int b = threadIdx.x;
    __shared__ double ds[64], dq[64];
    ds[b] = (double)g_psum[b * 64 + c];
    dq[b] = (double)g_psumsq[b * 64 + c];
    __syncthreads();
    #pragma unroll
    for (int off = 32; off > 0; off >>= 1) {
        if (b < off) { ds[b] += ds[b + off]; dq[b] += dq[b + off]; }
        __syncthreads();
    }
    if (b == 0) {
        const double mean = ds[0] / 480000.0;
        const double var  = dq[0] / 480000.0 - mean * mean;
        const double rstd = 1.0 / sqrt(var + 1e-5);
        const float sc = (float)((double)gamma[c] * rstd);
        g_scale[c] = sc;
        g_shift[c] = beta[c] - (float)mean * sc;
    }
}

// ---------------------------------------------------------------------------
// Kernel 5: in-place normalize. float4; 1875 float4 per (b,c) chunk.
// grid 30000, block 256 -> exactly 7,680,000 float4.
// ---------------------------------------------------------------------------
__global__ __launch_bounds__(256) void k_bn(float* __restrict__ out) {
    const int i = blockIdx.x * 256 + threadIdx.x;
    if (i >= 7680000) return;
    const int c = (i / 1875) & 63;
    const float sc = g_scale[c];
    const float sh = g_shift[c];
    float4 v = reinterpret_cast<float4*>(out)[i];
    v.x = fmaf(v.x, sc, sh);
    v.y = fmaf(v.y, sc, sh);
    v.z = fmaf(v.z, sc, sh);
    v.w = fmaf(v.w, sc, sh);
    reinterpret_cast<float4*>(out)[i] = v;
}

// ---------------------------------------------------------------------------
extern "C" void kernel_launch(void* const* d_in, const int* in_sizes, int n_in,
                              void* d_out, int out_size) {
    const float* x     = (const float*)d_in[0];
    const float* W     = (const float*)d_in[1];
    const float* bias  = (const float*)d_in[2];
    const float* A     = (const float*)d_in[3];
    const float* gamma = (const float*)d_in[4];
    const float* beta  = (const float*)d_in[5];
    float* out = (float*)d_out;

    k_conv  <<<dim3(3750, 3), 256>>>(x, W, bias);
    k_graph <<<9600, 256>>>(A, out);
    k_stats1<<<4096, 256>>>(out);
    k_stats2<<<64, 64>>>(gamma, beta);
    k_bn    <<<30000, 256>>>(out);
}